// round 4
// baseline (speedup 1.0000x reference)
#include <cuda_runtime.h>
#include <cstddef>

// Croston's method, two-pass segmented scan.
// Pass A: per-(row,segment) affine state map  (Z,V,q) -> (A*Z+B, A*V+C*q+D, E*q+F)
// Pass B: apply predecessor maps to initial state, replay segment, emit out=Z/V.

static constexpr int T_LEN  = 2048;
static constexpr int SEGS   = 16;
static constexpr int SEGLEN = T_LEN / SEGS;        // 128
static constexpr int NCHUNK = SEGLEN / 8;          // 16 chunks of 8 floats (32B)
static constexpr int B_ROWS = 8192;

// scratch: 8 floats per (row,segment) map (padded to 32B)
__device__ float g_maps[(size_t)B_ROWS * SEGS * 8];

__global__ __launch_bounds__(256) void croston_maps_kernel(
    const float* __restrict__ x,
    const float* __restrict__ alpha,
    float* __restrict__ maps)
{
    int tid = blockIdx.x * blockDim.x + threadIdx.x;
    if (tid >= B_ROWS * SEGS) return;
    int b = tid / SEGS;
    int s = tid % SEGS;

    float a   = __ldg(alpha);
    float oma = 1.0f - a;

    const float4* xs = reinterpret_cast<const float4*>(
        x + (size_t)b * T_LEN + (size_t)s * SEGLEN);

    // affine map accumulators
    float A = 1.0f, Bz = 0.0f, C = 0.0f, D = 0.0f, E = 1.0f, F = 0.0f;

    float4 c0 = xs[0];
    float4 c1 = xs[1];
    #pragma unroll 4
    for (int i = 0; i < NCHUNK; i++) {
        float4 n0, n1;
        if (i + 1 < NCHUNK) {
            n0 = xs[2 * i + 2];
            n1 = xs[2 * i + 3];
        }
        float xv[8] = {c0.x, c0.y, c0.z, c0.w, c1.x, c1.y, c1.z, c1.w};
        #pragma unroll
        for (int j = 0; j < 8; j++) {
            float xt = xv[j];
            bool nz = (xt != 0.0f);
            float An  = oma * A;
            float Bzn = fmaf(a, xt, oma * Bz);
            float Cn  = fmaf(a, E, oma * C);
            float Dn  = fmaf(a, F, oma * D);
            A  = nz ? An  : A;
            Bz = nz ? Bzn : Bz;
            C  = nz ? Cn  : C;
            D  = nz ? Dn  : D;
            E  = nz ? 0.0f : E;
            F  = nz ? 1.0f : (F + 1.0f);
        }
        c0 = n0;
        c1 = n1;
    }

    float4* mv = reinterpret_cast<float4*>(maps + (size_t)tid * 8);
    mv[0] = make_float4(A, Bz, C, D);
    mv[1] = make_float4(E, F, 0.0f, 0.0f);
}

__global__ __launch_bounds__(256) void croston_scan_kernel(
    const float* __restrict__ x,
    const float* __restrict__ alpha,
    const float* __restrict__ Z0,
    const float* __restrict__ V0,
    const float* __restrict__ q0,
    const float* __restrict__ maps,
    float* __restrict__ out)
{
    int tid = blockIdx.x * blockDim.x + threadIdx.x;
    if (tid >= B_ROWS * SEGS) return;
    int b = tid / SEGS;
    int s = tid % SEGS;

    float a   = __ldg(alpha);
    float oma = 1.0f - a;

    float Z = __ldg(Z0 + b);
    float V = __ldg(V0 + b);
    float q = __ldg(q0 + b);

    // Apply predecessor segment maps to get this segment's initial state.
    const float4* mv = reinterpret_cast<const float4*>(
        maps + (size_t)b * SEGS * 8);
    for (int j = 0; j < s; j++) {
        float4 m0 = mv[2 * j];
        float4 m1 = mv[2 * j + 1];
        float Zn = fmaf(m0.x, Z, m0.y);
        float Vn = fmaf(m0.x, V, fmaf(m0.z, q, m0.w));
        float qn = fmaf(m1.x, q, m1.y);
        Z = Zn; V = Vn; q = qn;
    }

    const float4* xs = reinterpret_cast<const float4*>(
        x + (size_t)b * T_LEN + (size_t)s * SEGLEN);
    float4* os = reinterpret_cast<float4*>(
        out + (size_t)b * T_LEN + (size_t)s * SEGLEN);

    float4 c0 = xs[0];
    float4 c1 = xs[1];
    #pragma unroll 4
    for (int i = 0; i < NCHUNK; i++) {
        float4 n0, n1;
        if (i + 1 < NCHUNK) {
            n0 = xs[2 * i + 2];
            n1 = xs[2 * i + 3];
        }
        float xv[8] = {c0.x, c0.y, c0.z, c0.w, c1.x, c1.y, c1.z, c1.w};
        float ov[8];
        #pragma unroll
        for (int j = 0; j < 8; j++) {
            float xt = xv[j];
            float Zn = fmaf(a, xt, oma * Z);
            float Vn = fmaf(a, q,  oma * V);
            bool nz = (xt != 0.0f);
            Z = nz ? Zn : Z;
            V = nz ? Vn : V;
            q = nz ? 1.0f : (q + 1.0f);
            ov[j] = __fdividef(Z, V);
        }
        os[2 * i]     = make_float4(ov[0], ov[1], ov[2], ov[3]);
        os[2 * i + 1] = make_float4(ov[4], ov[5], ov[6], ov[7]);
        c0 = n0;
        c1 = n1;
    }
}

extern "C" void kernel_launch(void* const* d_in, const int* in_sizes, int n_in,
                              void* d_out, int out_size)
{
    const float* x     = (const float*)d_in[0];
    const float* alpha = (const float*)d_in[1];
    const float* Z0    = (const float*)d_in[2];
    const float* V0    = (const float*)d_in[3];
    const float* q0    = (const float*)d_in[4];
    float* out = (float*)d_out;

    float* maps = nullptr;
    cudaGetSymbolAddress((void**)&maps, g_maps);

    int total = B_ROWS * SEGS;
    int threads = 256;
    int blocks = (total + threads - 1) / threads;

    croston_maps_kernel<<<blocks, threads>>>(x, alpha, maps);
    croston_scan_kernel<<<blocks, threads>>>(x, alpha, Z0, V0, q0, maps, out);
}

// round 5
// speedup vs baseline: 1.0445x; 1.0445x over previous
#include <cuda_runtime.h>
#include <cstddef>

// Croston's method, two-pass segmented scan, SEGS=64 for MLP/occupancy.
// Pass A: per-(row,segment) affine state map  (Z,V,q) -> (A*Z+B, A*V+C*q+D, E*q+F)
// Pass B: stage row maps in smem, apply predecessors, replay segment, out=Z/V.

static constexpr int T_LEN   = 2048;
static constexpr int SEGS    = 64;
static constexpr int SEGLEN  = T_LEN / SEGS;       // 32 floats = 8 float4
static constexpr int NV4     = SEGLEN / 4;         // 8
static constexpr int B_ROWS  = 8192;
static constexpr int THREADS = 256;
static constexpr int ROWS_PER_BLK = THREADS / SEGS; // 4

// scratch: 8 floats (32B) per (row,segment) map -> 16 MB
__device__ float g_maps[(size_t)B_ROWS * SEGS * 8];

__global__ __launch_bounds__(THREADS, 4) void croston_maps_kernel(
    const float* __restrict__ x,
    const float* __restrict__ alpha,
    float* __restrict__ maps)
{
    int tid = blockIdx.x * blockDim.x + threadIdx.x;
    int b = tid >> 6;        // tid / SEGS
    int s = tid & (SEGS - 1);

    float a   = __ldg(alpha);
    float oma = 1.0f - a;

    const float4* xs = reinterpret_cast<const float4*>(
        x + (size_t)b * T_LEN + (size_t)s * SEGLEN);

    // Preload the whole segment: 8 independent LDG.128 in flight.
    float4 r[NV4];
    #pragma unroll
    for (int i = 0; i < NV4; i++) r[i] = xs[i];

    // affine map accumulators
    float A = 1.0f, Bz = 0.0f, C = 0.0f, D = 0.0f, E = 1.0f, F = 0.0f;

    #pragma unroll
    for (int i = 0; i < NV4; i++) {
        float xv[4] = {r[i].x, r[i].y, r[i].z, r[i].w};
        #pragma unroll
        for (int j = 0; j < 4; j++) {
            float xt = xv[j];
            bool nz = (xt != 0.0f);
            float An  = oma * A;
            float Bzn = fmaf(a, xt, oma * Bz);
            float Cn  = fmaf(a, E, oma * C);
            float Dn  = fmaf(a, F, oma * D);
            A  = nz ? An  : A;
            Bz = nz ? Bzn : Bz;
            C  = nz ? Cn  : C;
            D  = nz ? Dn  : D;
            E  = nz ? 0.0f : E;
            F  = nz ? 1.0f : (F + 1.0f);
        }
    }

    float4* mv = reinterpret_cast<float4*>(maps + (size_t)tid * 8);
    mv[0] = make_float4(A, Bz, C, D);
    mv[1] = make_float4(E, F, 0.0f, 0.0f);
}

__global__ __launch_bounds__(THREADS, 4) void croston_scan_kernel(
    const float* __restrict__ x,
    const float* __restrict__ alpha,
    const float* __restrict__ Z0,
    const float* __restrict__ V0,
    const float* __restrict__ q0,
    const float* __restrict__ maps,
    float* __restrict__ out)
{
    __shared__ float4 smaps[ROWS_PER_BLK * SEGS * 2];   // 8 KB

    int tid = blockIdx.x * blockDim.x + threadIdx.x;
    int b = tid >> 6;
    int s = tid & (SEGS - 1);

    // Cooperative, coalesced staging of this block's 4 rows of maps.
    {
        int b0 = (blockIdx.x * THREADS) >> 6;   // first row of block
        const float4* gsrc = reinterpret_cast<const float4*>(
            maps + (size_t)b0 * SEGS * 8);
        #pragma unroll
        for (int i = 0; i < 2; i++)
            smaps[threadIdx.x + i * THREADS] = gsrc[threadIdx.x + i * THREADS];
    }

    float a   = __ldg(alpha);
    float oma = 1.0f - a;

    const float4* xs = reinterpret_cast<const float4*>(
        x + (size_t)b * T_LEN + (size_t)s * SEGLEN);

    // Preload the whole segment (8 LDG.128 in flight) before the smem barrier.
    float4 r[NV4];
    #pragma unroll
    for (int i = 0; i < NV4; i++) r[i] = xs[i];

    float Z = __ldg(Z0 + b);
    float V = __ldg(V0 + b);
    float q = __ldg(q0 + b);

    __syncthreads();

    // Apply predecessor segment maps (uniform/broadcast smem reads).
    {
        int rbase = ((threadIdx.x >> 6) * SEGS) * 2;  // row-local map base (float4 idx)
        for (int j = 0; j < s; j++) {
            float4 m0 = smaps[rbase + 2 * j];
            float4 m1 = smaps[rbase + 2 * j + 1];
            float Zn = fmaf(m0.x, Z, m0.y);
            float Vn = fmaf(m0.x, V, fmaf(m0.z, q, m0.w));
            float qn = fmaf(m1.x, q, m1.y);
            Z = Zn; V = Vn; q = qn;
        }
    }

    float4* os = reinterpret_cast<float4*>(
        out + (size_t)b * T_LEN + (size_t)s * SEGLEN);

    #pragma unroll
    for (int i = 0; i < NV4; i++) {
        float xv[4] = {r[i].x, r[i].y, r[i].z, r[i].w};
        float ov[4];
        #pragma unroll
        for (int j = 0; j < 4; j++) {
            float xt = xv[j];
            float Zn = fmaf(a, xt, oma * Z);
            float Vn = fmaf(a, q,  oma * V);
            bool nz = (xt != 0.0f);
            Z = nz ? Zn : Z;
            V = nz ? Vn : V;
            q = nz ? 1.0f : (q + 1.0f);
            ov[j] = __fdividef(Z, V);
        }
        os[i] = make_float4(ov[0], ov[1], ov[2], ov[3]);
    }
}

extern "C" void kernel_launch(void* const* d_in, const int* in_sizes, int n_in,
                              void* d_out, int out_size)
{
    const float* x     = (const float*)d_in[0];
    const float* alpha = (const float*)d_in[1];
    const float* Z0    = (const float*)d_in[2];
    const float* V0    = (const float*)d_in[3];
    const float* q0    = (const float*)d_in[4];
    float* out = (float*)d_out;

    float* maps = nullptr;
    cudaGetSymbolAddress((void**)&maps, g_maps);

    int total  = B_ROWS * SEGS;
    int blocks = total / THREADS;   // 2048

    croston_maps_kernel<<<blocks, THREADS>>>(x, alpha, maps);
    croston_scan_kernel<<<blocks, THREADS>>>(x, alpha, Z0, V0, q0, maps, out);
}

// round 6
// speedup vs baseline: 1.6933x; 1.6212x over previous
#include <cuda_runtime.h>
#include <cstddef>

// Croston's method — single fused kernel.
// Each block owns ROWS_PER_BLK=4 complete rows (T=2048). Flow:
//   1. cooperative coalesced load x -> padded smem
//   2. per-(row,segment) thread builds affine map (Z,V,q)->(A*Z+B, A*V+C*q+D, E*q+F)
//   3. apply predecessor maps (smem broadcast) to get segment-initial state
//   4. replay segment, out = Z/V written in-place into smem
//   5. cooperative coalesced store smem -> out

static constexpr int T_LEN   = 2048;
static constexpr int SEGS    = 64;
static constexpr int SEGLEN  = T_LEN / SEGS;       // 32
static constexpr int B_ROWS  = 8192;
static constexpr int THREADS = 256;
static constexpr int ROWS_PER_BLK = THREADS / SEGS;          // 4
static constexpr int SSTRIDE = SEGLEN + 1;                   // 33 floats, conflict-free
static constexpr int ROW_STRIDE = SEGS * SSTRIDE;            // 2112 floats
static constexpr int MSTRIDE = 9;                            // padded map stride

__global__ __launch_bounds__(THREADS, 5) void croston_fused_kernel(
    const float* __restrict__ x,
    const float* __restrict__ alpha,
    const float* __restrict__ Z0,
    const float* __restrict__ V0,
    const float* __restrict__ q0,
    float* __restrict__ out)
{
    __shared__ float sx[ROWS_PER_BLK * ROW_STRIDE];          // 33792 B
    __shared__ float smaps[ROWS_PER_BLK * SEGS * MSTRIDE];   //  9216 B

    int tx = threadIdx.x;
    int row0 = blockIdx.x * ROWS_PER_BLK;

    // ── 1. cooperative coalesced load: 4 rows × 512 float4 ──
    {
        const float4* gx = reinterpret_cast<const float4*>(
            x + (size_t)row0 * T_LEN);
        #pragma unroll
        for (int i = 0; i < 8; i++) {
            int p   = i * THREADS + tx;      // 0..2047 contiguous across block
            float4 v = gx[p];
            int row = p >> 9;                // p / 512
            int f   = p & 511;
            int s   = f >> 3;                // segment
            int j   = (f & 7) * 4;           // element within segment
            float* dst = sx + row * ROW_STRIDE + s * SSTRIDE + j;
            dst[0] = v.x; dst[1] = v.y; dst[2] = v.z; dst[3] = v.w;
        }
    }

    float a   = __ldg(alpha);
    float oma = 1.0f - a;

    int bl = tx >> 6;              // row within block (0..3)
    int s  = tx & (SEGS - 1);      // segment (0..63)
    int b  = row0 + bl;

    float* seg = sx + bl * ROW_STRIDE + s * SSTRIDE;

    __syncthreads();

    // ── 2. build this segment's affine map ──
    {
        float A = 1.0f, Bz = 0.0f, C = 0.0f, D = 0.0f, E = 1.0f, F = 0.0f;
        #pragma unroll
        for (int j = 0; j < SEGLEN; j++) {
            float xt = seg[j];
            bool nz = (xt != 0.0f);
            float An  = oma * A;
            float Bzn = fmaf(a, xt, oma * Bz);
            float Cn  = fmaf(a, E, oma * C);
            float Dn  = fmaf(a, F, oma * D);
            A  = nz ? An  : A;
            Bz = nz ? Bzn : Bz;
            C  = nz ? Cn  : C;
            D  = nz ? Dn  : D;
            E  = nz ? 0.0f : E;
            F  = nz ? 1.0f : (F + 1.0f);
        }
        float* mp = smaps + (bl * SEGS + s) * MSTRIDE;
        mp[0] = A; mp[1] = Bz; mp[2] = C; mp[3] = D; mp[4] = E; mp[5] = F;
    }

    float Z = __ldg(Z0 + b);
    float V = __ldg(V0 + b);
    float q = __ldg(q0 + b);

    __syncthreads();

    // ── 3. apply predecessor maps (broadcast smem reads) ──
    {
        const float* mrow = smaps + bl * SEGS * MSTRIDE;
        for (int j = 0; j < s; j++) {
            const float* m = mrow + j * MSTRIDE;
            float A = m[0], Bz = m[1], C = m[2], D = m[3], E = m[4], F = m[5];
            float Zn = fmaf(A, Z, Bz);
            float Vn = fmaf(A, V, fmaf(C, q, D));
            float qn = fmaf(E, q, F);
            Z = Zn; V = Vn; q = qn;
        }
    }

    // ── 4. replay segment, write out in-place (thread-private slots) ──
    #pragma unroll
    for (int j = 0; j < SEGLEN; j++) {
        float xt = seg[j];
        float Zn = fmaf(a, xt, oma * Z);
        float Vn = fmaf(a, q,  oma * V);
        bool nz = (xt != 0.0f);
        Z = nz ? Zn : Z;
        V = nz ? Vn : V;
        q = nz ? 1.0f : (q + 1.0f);
        seg[j] = __fdividef(Z, V);
    }

    __syncthreads();

    // ── 5. cooperative coalesced store ──
    {
        float4* gout = reinterpret_cast<float4*>(
            out + (size_t)row0 * T_LEN);
        #pragma unroll
        for (int i = 0; i < 8; i++) {
            int p   = i * THREADS + tx;
            int row = p >> 9;
            int f   = p & 511;
            int sg  = f >> 3;
            int j   = (f & 7) * 4;
            const float* src = sx + row * ROW_STRIDE + sg * SSTRIDE + j;
            gout[p] = make_float4(src[0], src[1], src[2], src[3]);
        }
    }
}

extern "C" void kernel_launch(void* const* d_in, const int* in_sizes, int n_in,
                              void* d_out, int out_size)
{
    const float* x     = (const float*)d_in[0];
    const float* alpha = (const float*)d_in[1];
    const float* Z0    = (const float*)d_in[2];
    const float* V0    = (const float*)d_in[3];
    const float* q0    = (const float*)d_in[4];
    float* out = (float*)d_out;

    int blocks = B_ROWS / ROWS_PER_BLK;   // 2048
    croston_fused_kernel<<<blocks, THREADS>>>(x, alpha, Z0, V0, q0, out);
}

// round 7
// speedup vs baseline: 2.1333x; 1.2599x over previous
#include <cuda_runtime.h>
#include <cstddef>

// Croston's method — single fused kernel, issue-count optimized.
//   1. coalesced load x -> padded smem (float4 slots, conflict-free)
//   2. per-(row,segment) thread builds affine map in registers
//   3. Kogge-Stone shfl scan composes prefix maps (2 warps/row, smem fixup)
//   4. replay segment from smem float4s, out = Z/V written in place
//   5. coalesced store smem -> out

static constexpr int T_LEN   = 2048;
static constexpr int SEGS    = 64;
static constexpr int SEGLEN  = 32;
static constexpr int B_ROWS  = 8192;
static constexpr int THREADS = 256;
static constexpr int ROWS_PER_BLK = 4;
static constexpr int S4   = 9;             // float4 per segment slot (8 data + 1 pad)
static constexpr int ROW4 = SEGS * S4;     // 576 float4 per row

__global__ __launch_bounds__(THREADS, 5) void croston_fused_kernel(
    const float* __restrict__ x,
    const float* __restrict__ alpha,
    const float* __restrict__ Z0,
    const float* __restrict__ V0,
    const float* __restrict__ q0,
    float* __restrict__ out)
{
    __shared__ float4 sx[ROWS_PER_BLK * ROW4];      // 36864 B
    __shared__ float  swtot[ROWS_PER_BLK][8];       // lower-warp map totals

    int tx   = threadIdx.x;
    int row0 = blockIdx.x * ROWS_PER_BLK;

    // ── 1. coalesced load: 2048 float4, all STS.128 conflict-free ──
    {
        const float4* gx = reinterpret_cast<const float4*>(
            x + (size_t)row0 * T_LEN);
        #pragma unroll
        for (int i = 0; i < 8; i++) {
            int p = i * THREADS + tx;
            float4 v = gx[p];
            int row = p >> 9, f = p & 511, sg = f >> 3, k = f & 7;
            sx[row * ROW4 + sg * S4 + k] = v;
        }
    }

    float a = __ldg(alpha);

    int bl   = tx >> 6;            // row within block
    int s    = tx & (SEGS - 1);    // segment
    int b    = row0 + bl;
    int lane = tx & 31;
    int half = (tx >> 5) & 1;      // 0: segs 0..31, 1: segs 32..63

    __syncthreads();

    float4* seg4 = &sx[bl * ROW4 + s * S4];

    // ── 2. build affine map (Z,V,q) -> (A*Z+Bz, A*V+C*q+D, E*q+F) ──
    float A = 1.0f, Bz = 0.0f, C = 0.0f, D = 0.0f, E = 1.0f, F = 0.0f;
    #pragma unroll
    for (int i = 0; i < 8; i++) {
        float4 v = seg4[i];
        float xv[4] = {v.x, v.y, v.z, v.w};
        #pragma unroll
        for (int j = 0; j < 4; j++) {
            float xt  = xv[j];
            bool  nz  = (xt != 0.0f);
            float anz = nz ? a : 0.0f;
            Bz = fmaf(anz, xt - Bz, Bz);
            C  = fmaf(anz, E  - C,  C);   // uses pre-update E
            D  = fmaf(anz, F  - D,  D);   // uses pre-update F
            A  = fmaf(anz, -A, A);
            E  = nz ? 0.0f : E;
            F  = nz ? 1.0f : (F + 1.0f);
        }
    }

    // ── 3. Kogge-Stone inclusive scan of maps within each warp ──
    // combine: my = my ∘ prev  (prev applied first)
    #pragma unroll
    for (int d = 1; d < 32; d <<= 1) {
        float pA = __shfl_up_sync(0xffffffffu, A,  d);
        float pB = __shfl_up_sync(0xffffffffu, Bz, d);
        float pC = __shfl_up_sync(0xffffffffu, C,  d);
        float pD = __shfl_up_sync(0xffffffffu, D,  d);
        float pE = __shfl_up_sync(0xffffffffu, E,  d);
        float pF = __shfl_up_sync(0xffffffffu, F,  d);
        if (lane >= d) {
            Bz = fmaf(A, pB, Bz);
            D  = fmaf(A, pD, fmaf(C, pF, D));
            C  = fmaf(A, pC, C * pE);
            F  = fmaf(E, pF, F);
            A  = A * pA;
            E  = E * pE;
        }
    }

    // lower warp of each row publishes its inclusive total
    if (half == 0 && lane == 31) {
        float* w = swtot[bl];
        w[0] = A; w[1] = Bz; w[2] = C; w[3] = D; w[4] = E; w[5] = F;
    }

    // exclusive shift (lane 0 = identity map)
    {
        float eA = __shfl_up_sync(0xffffffffu, A,  1);
        float eB = __shfl_up_sync(0xffffffffu, Bz, 1);
        float eC = __shfl_up_sync(0xffffffffu, C,  1);
        float eD = __shfl_up_sync(0xffffffffu, D,  1);
        float eE = __shfl_up_sync(0xffffffffu, E,  1);
        float eF = __shfl_up_sync(0xffffffffu, F,  1);
        bool l0 = (lane == 0);
        A  = l0 ? 1.0f : eA;
        Bz = l0 ? 0.0f : eB;
        C  = l0 ? 0.0f : eC;
        D  = l0 ? 0.0f : eD;
        E  = l0 ? 1.0f : eE;
        F  = l0 ? 0.0f : eF;
    }

    __syncthreads();

    // upper warp composes with lower warp's total (lower applied first)
    if (half == 1) {
        const float* w = swtot[bl];
        float pA = w[0], pB = w[1], pC = w[2], pD = w[3], pE = w[4], pF = w[5];
        Bz = fmaf(A, pB, Bz);
        D  = fmaf(A, pD, fmaf(C, pF, D));
        C  = fmaf(A, pC, C * pE);
        F  = fmaf(E, pF, F);
        A  = A * pA;
        E  = E * pE;
    }

    // apply exclusive-prefix map to initial state
    float Zi = __ldg(Z0 + b), Vi = __ldg(V0 + b), qi = __ldg(q0 + b);
    float Z = fmaf(A, Zi, Bz);
    float V = fmaf(A, Vi, fmaf(C, qi, D));
    float q = fmaf(E, qi, F);

    // ── 4. replay segment, write out in place ──
    #pragma unroll
    for (int i = 0; i < 8; i++) {
        float4 v = seg4[i];
        float xv[4] = {v.x, v.y, v.z, v.w};
        float ov[4];
        #pragma unroll
        for (int j = 0; j < 4; j++) {
            float xt  = xv[j];
            bool  nz  = (xt != 0.0f);
            float anz = nz ? a : 0.0f;
            Z = fmaf(anz, xt - Z, Z);
            V = fmaf(anz, q  - V, V);
            q = nz ? 1.0f : (q + 1.0f);
            ov[j] = __fdividef(Z, V);
        }
        seg4[i] = make_float4(ov[0], ov[1], ov[2], ov[3]);
    }

    __syncthreads();

    // ── 5. coalesced store ──
    {
        float4* gout = reinterpret_cast<float4*>(
            out + (size_t)row0 * T_LEN);
        #pragma unroll
        for (int i = 0; i < 8; i++) {
            int p = i * THREADS + tx;
            int row = p >> 9, f = p & 511, sg = f >> 3, k = f & 7;
            gout[p] = sx[row * ROW4 + sg * S4 + k];
        }
    }
}

extern "C" void kernel_launch(void* const* d_in, const int* in_sizes, int n_in,
                              void* d_out, int out_size)
{
    const float* x     = (const float*)d_in[0];
    const float* alpha = (const float*)d_in[1];
    const float* Z0    = (const float*)d_in[2];
    const float* V0    = (const float*)d_in[3];
    const float* q0    = (const float*)d_in[4];
    float* out = (float*)d_out;

    croston_fused_kernel<<<B_ROWS / ROWS_PER_BLK, THREADS>>>(
        x, alpha, Z0, V0, q0, out);
}

// round 9
// speedup vs baseline: 2.4105x; 1.1299x over previous
#include <cuda_runtime.h>
#include <cstddef>

// Croston's method — single fused kernel, round 7.
// 128-thread blocks (2 rows each) for 10 blocks/SM occupancy and fine
// wave granularity; staging smem index is m(p) = p + (p>>3) (pad float4
// every 8) so address math is 2 ALU ops; segment base is tx*9.

static constexpr int T_LEN   = 2048;
static constexpr int SEGS    = 64;
static constexpr int SEGLEN  = 32;
static constexpr int B_ROWS  = 8192;
static constexpr int THREADS = 128;
static constexpr int ROWS_PER_BLK = 2;
static constexpr int S4   = 9;                       // float4 per segment slot
static constexpr int NF4  = ROWS_PER_BLK * T_LEN / 4;   // 1024 float4 per block

__global__ __launch_bounds__(THREADS, 10) void croston_fused_kernel(
    const float* __restrict__ x,
    const float* __restrict__ alpha,
    const float* __restrict__ Z0,
    const float* __restrict__ V0,
    const float* __restrict__ q0,
    float* __restrict__ out)
{
    __shared__ float4 sx[ROWS_PER_BLK * SEGS * S4];   // 18432 B
    __shared__ float  swtot[ROWS_PER_BLK][8];         // lower-warp map totals

    int tx   = threadIdx.x;
    int row0 = blockIdx.x * ROWS_PER_BLK;

    // ── 1. coalesced load: 1024 float4; smem slot = p + (p>>3) ──
    {
        const float4* gx = reinterpret_cast<const float4*>(
            x + (size_t)row0 * T_LEN);
        #pragma unroll
        for (int i = 0; i < 8; i++) {
            int p = i * THREADS + tx;
            sx[p + (p >> 3)] = gx[p];
        }
    }

    float a = __ldg(alpha);

    int bl   = tx >> 6;            // row within block
    int b    = row0 + bl;
    int lane = tx & 31;
    int half = (tx >> 5) & 1;      // 0: segs 0..31, 1: segs 32..63

    float Zi = __ldg(Z0 + b);
    float Vi = __ldg(V0 + b);
    float qi = __ldg(q0 + b);

    __syncthreads();

    float4* seg4 = &sx[tx * S4];   // bl*SEGS*S4 + s*S4 == tx*9

    // ── 2. build affine map (Z,V,q) -> (A*Z+Bz, A*V+C*q+D, E*q+F) ──
    float A = 1.0f, Bz = 0.0f, C = 0.0f, D = 0.0f, E = 1.0f, F = 0.0f;
    #pragma unroll
    for (int i = 0; i < 8; i++) {
        float4 v = seg4[i];
        float xv[4] = {v.x, v.y, v.z, v.w};
        #pragma unroll
        for (int j = 0; j < 4; j++) {
            float xt  = xv[j];
            bool  nz  = (xt != 0.0f);
            float anz = nz ? a : 0.0f;
            Bz = fmaf(anz, xt - Bz, Bz);
            C  = fmaf(anz, E  - C,  C);   // uses pre-update E
            D  = fmaf(anz, F  - D,  D);   // uses pre-update F
            A  = fmaf(anz, -A, A);
            E  = nz ? 0.0f : E;
            F  = nz ? 1.0f : (F + 1.0f);
        }
    }

    // ── 3. Kogge-Stone inclusive scan of maps within each warp ──
    #pragma unroll
    for (int d = 1; d < 32; d <<= 1) {
        float pA = __shfl_up_sync(0xffffffffu, A,  d);
        float pB = __shfl_up_sync(0xffffffffu, Bz, d);
        float pC = __shfl_up_sync(0xffffffffu, C,  d);
        float pD = __shfl_up_sync(0xffffffffu, D,  d);
        float pE = __shfl_up_sync(0xffffffffu, E,  d);
        float pF = __shfl_up_sync(0xffffffffu, F,  d);
        if (lane >= d) {
            Bz = fmaf(A, pB, Bz);
            D  = fmaf(A, pD, fmaf(C, pF, D));
            C  = fmaf(A, pC, C * pE);
            F  = fmaf(E, pF, F);
            A  = A * pA;
            E  = E * pE;
        }
    }

    // lower warp of each row publishes its inclusive total
    if (half == 0 && lane == 31) {
        float* w = swtot[bl];
        w[0] = A; w[1] = Bz; w[2] = C; w[3] = D; w[4] = E; w[5] = F;
    }

    // exclusive shift (lane 0 = identity map)
    {
        float eA = __shfl_up_sync(0xffffffffu, A,  1);
        float eB = __shfl_up_sync(0xffffffffu, Bz, 1);
        float eC = __shfl_up_sync(0xffffffffu, C,  1);
        float eD = __shfl_up_sync(0xffffffffu, D,  1);
        float eE = __shfl_up_sync(0xffffffffu, E,  1);
        float eF = __shfl_up_sync(0xffffffffu, F,  1);
        bool l0 = (lane == 0);
        A  = l0 ? 1.0f : eA;
        Bz = l0 ? 0.0f : eB;
        C  = l0 ? 0.0f : eC;
        D  = l0 ? 0.0f : eD;
        E  = l0 ? 1.0f : eE;
        F  = l0 ? 0.0f : eF;
    }

    __syncthreads();

    // upper warp composes with lower warp's total (lower applied first)
    if (half == 1) {
        const float* w = swtot[bl];
        float pA = w[0], pB = w[1], pC = w[2], pD = w[3], pE = w[4], pF = w[5];
        Bz = fmaf(A, pB, Bz);
        D  = fmaf(A, pD, fmaf(C, pF, D));
        C  = fmaf(A, pC, C * pE);
        F  = fmaf(E, pF, F);
        A  = A * pA;
        E  = E * pE;
    }

    // apply exclusive-prefix map to initial state
    float Z = fmaf(A, Zi, Bz);
    float V = fmaf(A, Vi, fmaf(C, qi, D));
    float q = fmaf(E, qi, F);

    // ── 4. replay segment, write out in place ──
    #pragma unroll
    for (int i = 0; i < 8; i++) {
        float4 v = seg4[i];
        float xv[4] = {v.x, v.y, v.z, v.w};
        float ov[4];
        #pragma unroll
        for (int j = 0; j < 4; j++) {
            float xt  = xv[j];
            bool  nz  = (xt != 0.0f);
            float anz = nz ? a : 0.0f;
            Z = fmaf(anz, xt - Z, Z);
            V = fmaf(anz, q  - V, V);
            q = nz ? 1.0f : (q + 1.0f);
            ov[j] = __fdividef(Z, V);
        }
        seg4[i] = make_float4(ov[0], ov[1], ov[2], ov[3]);
    }

    __syncthreads();

    // ── 5. coalesced store ──
    {
        float4* gout = reinterpret_cast<float4*>(
            out + (size_t)row0 * T_LEN);
        #pragma unroll
        for (int i = 0; i < 8; i++) {
            int p = i * THREADS + tx;
            gout[p] = sx[p + (p >> 3)];
        }
    }
}

extern "C" void kernel_launch(void* const* d_in, const int* in_sizes, int n_in,
                              void* d_out, int out_size)
{
    const float* x     = (const float*)d_in[0];
    const float* alpha = (const float*)d_in[1];
    const float* Z0    = (const float*)d_in[2];
    const float* V0    = (const float*)d_in[3];
    const float* q0    = (const float*)d_in[4];
    float* out = (float*)d_out;

    croston_fused_kernel<<<B_ROWS / ROWS_PER_BLK, THREADS>>>(
        x, alpha, Z0, V0, q0, out);
}

// round 10
// speedup vs baseline: 2.4264x; 1.0066x over previous
#include <cuda_runtime.h>
#include <cstddef>
#include <cstdint>

// Croston's method — fused kernel, round 10.
// 64-thread blocks, one row per block (21 blocks/SM). cp.async staging.
// Phase-2 affine map tracks only (A,Bz,D,F); C and E derived post-loop:
//   C = anyNz ? A*a/(1-a) : 0,  E = anyNz ? 0 : 1.

static constexpr int T_LEN   = 2048;
static constexpr int SEGS    = 64;
static constexpr int B_ROWS  = 8192;
static constexpr int THREADS = 64;
static constexpr int S4      = 9;          // float4 per segment slot (8 data + pad)

__device__ __forceinline__ uint32_t smem_u32(const void* p) {
    uint32_t a;
    asm("{ .reg .u64 t; cvta.to.shared.u64 t, %1; cvt.u32.u64 %0, t; }"
        : "=r"(a) : "l"(p));
    return a;
}

__global__ __launch_bounds__(THREADS, 21) void croston_fused_kernel(
    const float* __restrict__ x,
    const float* __restrict__ alpha,
    const float* __restrict__ Z0,
    const float* __restrict__ V0,
    const float* __restrict__ q0,
    float* __restrict__ out)
{
    __shared__ float4 sx[SEGS * S4];   // 9216 B
    __shared__ float  swtot[8];        // lower-warp map total

    int tx = threadIdx.x;              // == segment index s
    int b  = blockIdx.x;               // row

    // ── 1. staging via cp.async: 512 float4, slot = p + (p>>3) ──
    {
        const float4* gx = reinterpret_cast<const float4*>(x + (size_t)b * T_LEN);
        #pragma unroll
        for (int i = 0; i < 8; i++) {
            int p = i * THREADS + tx;
            uint32_t dst = smem_u32(&sx[p + (p >> 3)]);
            asm volatile("cp.async.cg.shared.global [%0], [%1], 16;\n"
                         :: "r"(dst), "l"(gx + p));
        }
        asm volatile("cp.async.commit_group;\n");
    }

    float a   = __ldg(alpha);
    float oma = 1.0f - a;
    float kc  = __fdividef(a, oma);    // a/(1-a)

    int lane = tx & 31;
    int half = tx >> 5;                // 0: segs 0..31, 1: segs 32..63

    float Zi = __ldg(Z0 + b);
    float Vi = __ldg(V0 + b);
    float qi = __ldg(q0 + b);

    asm volatile("cp.async.wait_group 0;\n" ::: "memory");
    __syncthreads();

    float4* seg4 = &sx[tx * S4];

    // ── 2. build affine map (Z,V,q) -> (A*Z+Bz, A*V+C*q+D, E*q+F) ──
    float A = 1.0f, Bz = 0.0f, D = 0.0f, F = 0.0f;
    bool anyNz = false;
    #pragma unroll
    for (int i = 0; i < 8; i++) {
        float4 v = seg4[i];
        float xv[4] = {v.x, v.y, v.z, v.w};
        #pragma unroll
        for (int j = 0; j < 4; j++) {
            float xt  = xv[j];
            bool  nz  = (xt != 0.0f);
            float anz = nz ? a : 0.0f;
            Bz = fmaf(anz, xt - Bz, Bz);
            D  = fmaf(anz, F  - D,  D);   // uses pre-update F
            A  = fmaf(anz, -A, A);
            F  = nz ? 1.0f : (F + 1.0f);
            anyNz = anyNz | nz;
        }
    }
    float E = anyNz ? 0.0f : 1.0f;
    float C = anyNz ? A * kc : 0.0f;

    // ── 3. Kogge-Stone inclusive scan of maps within each warp ──
    // combine: my = my ∘ prev  (prev applied first)
    #pragma unroll
    for (int d = 1; d < 32; d <<= 1) {
        float pA = __shfl_up_sync(0xffffffffu, A,  d);
        float pB = __shfl_up_sync(0xffffffffu, Bz, d);
        float pC = __shfl_up_sync(0xffffffffu, C,  d);
        float pD = __shfl_up_sync(0xffffffffu, D,  d);
        float pE = __shfl_up_sync(0xffffffffu, E,  d);
        float pF = __shfl_up_sync(0xffffffffu, F,  d);
        if (lane >= d) {
            Bz = fmaf(A, pB, Bz);
            D  = fmaf(A, pD, fmaf(C, pF, D));
            C  = fmaf(A, pC, C * pE);
            F  = fmaf(E, pF, F);
            A  = A * pA;
            E  = E * pE;
        }
    }

    // lower warp publishes its inclusive total
    if (half == 0 && lane == 31) {
        swtot[0] = A; swtot[1] = Bz; swtot[2] = C;
        swtot[3] = D; swtot[4] = E;  swtot[5] = F;
    }

    // exclusive shift (lane 0 = identity)
    {
        float eA = __shfl_up_sync(0xffffffffu, A,  1);
        float eB = __shfl_up_sync(0xffffffffu, Bz, 1);
        float eC = __shfl_up_sync(0xffffffffu, C,  1);
        float eD = __shfl_up_sync(0xffffffffu, D,  1);
        float eE = __shfl_up_sync(0xffffffffu, E,  1);
        float eF = __shfl_up_sync(0xffffffffu, F,  1);
        bool l0 = (lane == 0);
        A  = l0 ? 1.0f : eA;
        Bz = l0 ? 0.0f : eB;
        C  = l0 ? 0.0f : eC;
        D  = l0 ? 0.0f : eD;
        E  = l0 ? 1.0f : eE;
        F  = l0 ? 0.0f : eF;
    }

    __syncthreads();

    // upper warp composes with lower warp's total (lower applied first)
    if (half == 1) {
        float pA = swtot[0], pB = swtot[1], pC = swtot[2];
        float pD = swtot[3], pE = swtot[4], pF = swtot[5];
        Bz = fmaf(A, pB, Bz);
        D  = fmaf(A, pD, fmaf(C, pF, D));
        C  = fmaf(A, pC, C * pE);
        F  = fmaf(E, pF, F);
        A  = A * pA;
        E  = E * pE;
    }

    // apply exclusive-prefix map to initial state
    float Z = fmaf(A, Zi, Bz);
    float V = fmaf(A, Vi, fmaf(C, qi, D));
    float q = fmaf(E, qi, F);

    // ── 4. replay segment, write out in place ──
    #pragma unroll
    for (int i = 0; i < 8; i++) {
        float4 v = seg4[i];
        float xv[4] = {v.x, v.y, v.z, v.w};
        float ov[4];
        #pragma unroll
        for (int j = 0; j < 4; j++) {
            float xt  = xv[j];
            bool  nz  = (xt != 0.0f);
            float anz = nz ? a : 0.0f;
            Z = fmaf(anz, xt - Z, Z);
            V = fmaf(anz, q  - V, V);
            q = nz ? 1.0f : (q + 1.0f);
            ov[j] = __fdividef(Z, V);
        }
        seg4[i] = make_float4(ov[0], ov[1], ov[2], ov[3]);
    }

    __syncthreads();

    // ── 5. coalesced store ──
    {
        float4* gout = reinterpret_cast<float4*>(out + (size_t)b * T_LEN);
        #pragma unroll
        for (int i = 0; i < 8; i++) {
            int p = i * THREADS + tx;
            gout[p] = sx[p + (p >> 3)];
        }
    }
}

extern "C" void kernel_launch(void* const* d_in, const int* in_sizes, int n_in,
                              void* d_out, int out_size)
{
    const float* x     = (const float*)d_in[0];
    const float* alpha = (const float*)d_in[1];
    const float* Z0    = (const float*)d_in[2];
    const float* V0    = (const float*)d_in[3];
    const float* q0    = (const float*)d_in[4];
    float* out = (float*)d_out;

    croston_fused_kernel<<<B_ROWS, THREADS>>>(x, alpha, Z0, V0, q0, out);
}